// round 5
// baseline (speedup 1.0000x reference)
#include <cuda_runtime.h>
#include <cuda_fp16.h>
#include <cstdint>

// ============================================================================
// BG_LSTM: B=512, T=512, H=256, input size 1.
// Persistent HMMA kernel (tcgen05 is NOT available at the harness's .target
// sm_103 — uses family-agnostic mma.sync.m16n8k16 + ldmatrix instead).
// 128 CTAs = 4 batch-groups(M=128) x 32 hidden-tiles (8 hidden -> N=32 gate
// cols per CTA). Per step: D[128,32] = A[128,256] @ B[32,256]^T.
// Precision: h in fp16 (rel 2^-12), W_hh split fp16 hi+lo (2 MMA splits).
// h exchanged via L2 (double-buffered) + per-group release/acquire counter.
// ============================================================================

static constexpr int Bsz = 512, Tsz = 512, Hsz = 256;
static constexpr int MTILES = 4, NTILES = 32, GROUP = 32;
static constexpr int MB = 128, NCOL = 32, NH = 8;

// SMEM layout (bytes)
static constexpr int SM_BIAS = 0;                   // 32 floats
static constexpr int SM_WIH  = 128;                 // 32 floats
static constexpr int SM_A    = 1024;                // A tile 128x256 fp16 = 65536
static constexpr int SM_BHI  = SM_A + 65536;        // 66560 (128B aligned)
static constexpr int SM_BLO  = SM_BHI + 16384;      // 82944
static constexpr int SM_DST  = SM_BLO + 16384;      // 99328; 128*36*4 = 18432
static constexpr int SM_TOTAL = SM_DST + 18432;     // 117760

// Device scratch (static — no allocation)
__device__ __half g_h[2][Bsz * Hsz];        // double-buffered h state
__device__ int    g_cnt[MTILES][Tsz + 8];   // per-group step counters
__device__ float  g_part[Bsz][NTILES];      // fc partials

// ---------------------------------------------------------------------------
// helpers
// ---------------------------------------------------------------------------
__device__ __forceinline__ uint32_t smem_to_u32(const void* p) {
    uint32_t a;
    asm("{ .reg .u64 t; cvta.to.shared.u64 t, %1; cvt.u32.u64 %0, t; }"
        : "=r"(a) : "l"(p));
    return a;
}

// SW128-style swizzled offsets. bits[7:9] of the linear offset == (r&7), so the
// XOR mask is exactly ((r&7)<<4) applied to the 16B-unit bits.
__device__ __forceinline__ uint32_t aoff(int r, int c) {  // A: 128 rows x 256 fp16
    return (uint32_t)(((c >> 6) * 16 + (r >> 3)) * 1024)
         + (uint32_t)((r & 7) * 128)
         + (((uint32_t)((c & 63) * 2)) ^ ((uint32_t)(r & 7) << 4));
}
__device__ __forceinline__ uint32_t boff(int r, int c) {  // B: 32 rows x 256 fp16
    return (uint32_t)(((c >> 6) * 4 + (r >> 3)) * 1024)
         + (uint32_t)((r & 7) * 128)
         + (((uint32_t)((c & 63) * 2)) ^ ((uint32_t)(r & 7) << 4));
}

__device__ __forceinline__ void ldsm4(uint32_t* r, uint32_t addr) {
    asm volatile("ldmatrix.sync.aligned.m8n8.x4.shared.b16 {%0,%1,%2,%3}, [%4];"
        : "=r"(r[0]), "=r"(r[1]), "=r"(r[2]), "=r"(r[3]) : "r"(addr));
}

__device__ __forceinline__ void mma16816(float* c, const uint32_t* a,
                                         uint32_t b0, uint32_t b1) {
    asm volatile(
        "mma.sync.aligned.m16n8k16.row.col.f32.f16.f16.f32 "
        "{%0,%1,%2,%3}, {%4,%5,%6,%7}, {%8,%9}, {%0,%1,%2,%3};"
        : "+f"(c[0]), "+f"(c[1]), "+f"(c[2]), "+f"(c[3])
        : "r"(a[0]), "r"(a[1]), "r"(a[2]), "r"(a[3]), "r"(b0), "r"(b1));
}

__device__ __forceinline__ int ld_acquire(const int* p) {
    int v;
    asm volatile("ld.acquire.gpu.global.b32 %0, [%1];" : "=r"(v) : "l"(p) : "memory");
    return v;
}

__device__ __forceinline__ float sigf(float x) {
    return __fdividef(1.f, 1.f + __expf(-x));       // ex2.approx + rcp.approx
}
__device__ __forceinline__ float tanhf_acc(float x) {
    return __fdividef(2.f, 1.f + __expf(-2.f * x)) - 1.f;
}

// ---------------------------------------------------------------------------
// init: zero h buffers + counters (runs every graph replay)
// ---------------------------------------------------------------------------
__global__ void lstm_init_kernel() {
    int tid = blockIdx.x * blockDim.x + threadIdx.x;
    int nth = gridDim.x * blockDim.x;
    uint4 z = make_uint4(0, 0, 0, 0);
    uint4* p = reinterpret_cast<uint4*>(&g_h[0][0]);
    int n16 = (2 * Bsz * Hsz * 2) / 16;   // both buffers
    for (int i = tid; i < n16; i += nth) p[i] = z;
    int* c = &g_cnt[0][0];
    for (int i = tid; i < MTILES * (Tsz + 8); i += nth) c[i] = 0;
}

// ---------------------------------------------------------------------------
// main persistent kernel: 128 CTAs x 128 threads
// ---------------------------------------------------------------------------
__global__ void __launch_bounds__(128, 1) lstm_main_kernel(
    const float* __restrict__ x,     const float* __restrict__ W_ih,
    const float* __restrict__ W_hh,  const float* __restrict__ b_ih,
    const float* __restrict__ b_hh,  const float* __restrict__ W_fc,
    const float* __restrict__ b_fc,  float* __restrict__ out)
{
    extern __shared__ char smem[];
    const uint32_t sb = smem_to_u32(smem);
    const int tid = threadIdx.x, wid = tid >> 5, lid = tid & 31;
    const int bidx = blockIdx.x;
    const int mtile = bidx >> 5, ntile = bidx & 31;
    const int n0 = ntile * NH;
    const int mi = wid >> 1, ni = wid & 1;     // 2x2 warp split: m64 x n16

    // --- build stationary B (W_hh slice) hi/lo fp16, swizzled ---
    // CTA col c: gate = c&3, hidden j = c>>2  (gate-minor for epilogue locality)
    for (int idx = tid; idx < NCOL * Hsz; idx += 128) {
        int r = idx >> 8, c = idx & 255;
        int gate = r & 3, j = r >> 2;
        float w = W_hh[(gate * Hsz + n0 + j) * Hsz + c];
        __half hi = __float2half(w);
        __half lo = __float2half(w - __half2float(hi));
        uint32_t o = boff(r, c);
        *reinterpret_cast<__half*>(smem + SM_BHI + o) = hi;
        *reinterpret_cast<__half*>(smem + SM_BLO + o) = lo;
    }
    if (tid < NCOL) {
        int gate = tid & 3, j = tid >> 2;
        int grow = gate * Hsz + n0 + j;
        reinterpret_cast<float*>(smem + SM_BIAS)[tid] = b_ih[grow] + b_hh[grow];
        reinterpret_cast<float*>(smem + SM_WIH)[tid]  = W_ih[grow];
    }
    __syncthreads();

    // per-thread LSTM state: thread t owns batch row (mtile*128 + t), 8 units
    float cst[NH], hq[NH];
#pragma unroll
    for (int j = 0; j < NH; ++j) { cst[j] = 0.f; hq[j] = 0.f; }
    const int myrow = mtile * MB + tid;

    // ldmatrix lane-role constants
    const int matA = lid >> 3;                      // which 8x8 tile this lane addresses
    const int rA_l = (matA & 1) * 8 + (lid & 7);    // A: row within m16 tile
    const int cA_l = (matA >> 1) * 8;               // A: col half
    const int rB_l = ni * 16 + (matA >> 1) * 8 + (lid & 7);  // B: n row
    const int cB_l = (matA & 1) * 8;                // B: k half

    const float* bs = reinterpret_cast<const float*>(smem + SM_BIAS);
    const float* ws = reinterpret_cast<const float*>(smem + SM_WIH);

    for (int t = 0; t < Tsz; ++t) {
        // 1. wait for all 32 producers of h(t) in this batch-group
        if (t > 0 && tid == 0) {
            int spins = 0;
            while (ld_acquire(&g_cnt[mtile][t]) < GROUP && spins < (1 << 27)) ++spins;
        }
        __syncthreads();

        const float xv = x[myrow * Tsz + t];

        // 2. A-build: coalesced LDG of h(t), swizzled STS (warp w: rows 32w..+31)
        {
            const __half* hsrc = g_h[t & 1];
            const int c0 = lid * 8;
#pragma unroll 4
            for (int rr = 0; rr < 32; ++rr) {
                int r = wid * 32 + rr;
                uint4 v = *reinterpret_cast<const uint4*>(
                    hsrc + (mtile * MB + r) * Hsz + c0);
                *reinterpret_cast<uint4*>(smem + SM_A + aoff(r, c0)) = v;
            }
        }
        __syncthreads();

        // 3. MMA: acc[mt][nt] over k, 2 splits (B_hi + B_lo)
        float acc[4][2][4];
#pragma unroll
        for (int a = 0; a < 4; ++a)
#pragma unroll
            for (int b = 0; b < 2; ++b)
#pragma unroll
                for (int k = 0; k < 4; ++k) acc[a][b][k] = 0.f;

#pragma unroll
        for (int kt = 0; kt < 16; ++kt) {
            uint32_t afr[4][4];
#pragma unroll
            for (int mt = 0; mt < 4; ++mt)
                ldsm4(afr[mt], sb + SM_A + aoff(mi * 64 + mt * 16 + rA_l, kt * 16 + cA_l));
            uint32_t bh[4], bl[4];
            const uint32_t bro = boff(rB_l, kt * 16 + cB_l);
            ldsm4(bh, sb + SM_BHI + bro);
            ldsm4(bl, sb + SM_BLO + bro);
#pragma unroll
            for (int mt = 0; mt < 4; ++mt) {
                mma16816(acc[mt][0], afr[mt], bh[0], bh[1]);
                mma16816(acc[mt][1], afr[mt], bh[2], bh[3]);
                mma16816(acc[mt][0], afr[mt], bl[0], bl[1]);
                mma16816(acc[mt][1], afr[mt], bl[2], bl[3]);
            }
        }

        // 4. stage D to SMEM (pad 36 floats/row -> conflict-free)
        {
            const int r0 = mi * 64 + (lid >> 2);
            const int cc = ni * 16 + 2 * (lid & 3);
#pragma unroll
            for (int mt = 0; mt < 4; ++mt) {
#pragma unroll
                for (int nt = 0; nt < 2; ++nt) {
                    int row = r0 + mt * 16, col = cc + nt * 8;
                    *reinterpret_cast<float2*>(smem + SM_DST + (row * 36 + col) * 4) =
                        make_float2(acc[mt][nt][0], acc[mt][nt][1]);
                    *reinterpret_cast<float2*>(smem + SM_DST + ((row + 8) * 36 + col) * 4) =
                        make_float2(acc[mt][nt][2], acc[mt][nt][3]);
                }
            }
        }
        __syncthreads();

        // 5. epilogue: thread t = row t; gates -> c,h; pack h fp16; STG
        {
            const float* drow = reinterpret_cast<const float*>(smem + SM_DST) + tid * 36;
            uint32_t pk[4];
#pragma unroll
            for (int j = 0; j < NH; ++j) {
                float gi = drow[4 * j + 0] + xv * ws[4 * j + 0] + bs[4 * j + 0];
                float gf = drow[4 * j + 1] + xv * ws[4 * j + 1] + bs[4 * j + 1];
                float gg = drow[4 * j + 2] + xv * ws[4 * j + 2] + bs[4 * j + 2];
                float go = drow[4 * j + 3] + xv * ws[4 * j + 3] + bs[4 * j + 3];
                float i_ = sigf(gi), f_ = sigf(gf);
                float g_ = tanhf_acc(gg), o_ = sigf(go);
                cst[j] = f_ * cst[j] + i_ * g_;
                float h = o_ * tanhf_acc(cst[j]);
                hq[j] = h;
                unsigned short u = __half_as_ushort(__float2half(h));
                if (j & 1) pk[j >> 1] |= ((uint32_t)u) << 16;
                else       pk[j >> 1]  = (uint32_t)u;
            }
            *reinterpret_cast<uint4*>(&g_h[(t + 1) & 1][myrow * Hsz + n0]) =
                make_uint4(pk[0], pk[1], pk[2], pk[3]);
        }
        __syncthreads();
        if (tid == 0)
            asm volatile("red.release.gpu.global.add.s32 [%0], 1;"
                         :: "l"(&g_cnt[mtile][t + 1]) : "memory");
    }

    // --- FC head: relu(h) @ W_fc^T + b_fc, deterministic 2-phase reduce ---
    {
        float p = 0.f;
#pragma unroll
        for (int j = 0; j < NH; ++j) {
            float h = hq[j] > 0.f ? hq[j] : 0.f;
            p += h * W_fc[n0 + j];
        }
        g_part[myrow][ntile] = p;
        __syncthreads();
        if (tid == 0)
            asm volatile("red.release.gpu.global.add.s32 [%0], 1;"
                         :: "l"(&g_cnt[mtile][Tsz + 2]) : "memory");
        if (ntile == 0) {
            if (tid == 0) {
                int spins = 0;
                while (ld_acquire(&g_cnt[mtile][Tsz + 2]) < GROUP && spins < (1 << 27)) ++spins;
            }
            __syncthreads();
            float acc = b_fc[0];
#pragma unroll
            for (int nt = 0; nt < NTILES; ++nt) acc += g_part[myrow][nt];
            out[myrow] = acc;
        }
    }
}

// ---------------------------------------------------------------------------
// kernel_launch
// ---------------------------------------------------------------------------
extern "C" void kernel_launch(void* const* d_in, const int* in_sizes, int n_in,
                              void* d_out, int out_size) {
    (void)in_sizes; (void)n_in; (void)out_size;
    const float* x    = (const float*)d_in[0];
    const float* W_ih = (const float*)d_in[1];
    const float* W_hh = (const float*)d_in[2];
    const float* b_ih = (const float*)d_in[3];
    const float* b_hh = (const float*)d_in[4];
    const float* W_fc = (const float*)d_in[5];
    const float* b_fc = (const float*)d_in[6];
    float* out = (float*)d_out;

    cudaFuncSetAttribute(lstm_main_kernel,
                         cudaFuncAttributeMaxDynamicSharedMemorySize, SM_TOTAL);

    lstm_init_kernel<<<64, 256>>>();
    lstm_main_kernel<<<MTILES * NTILES, 128, SM_TOTAL>>>(
        x, W_ih, W_hh, b_ih, b_hh, W_fc, b_fc, out);
}